// round 15
// baseline (speedup 1.0000x reference)
#include <cuda_runtime.h>
#include <cuda_bf16.h>
#include <climits>
#include <stdint.h>

// ---------------- problem constants ----------------
#define NSEC 9
#define T_   30
#define H_   41
#define WD_  2048
#define FM_  50
#define KH_  6
#define KW_  40
#define WP_  502
#define THRESHF 23.0f
#define DELTA  0.30f
#define POOLED_ELEMS (NSEC*T_*FM_*WP_)   // 6,777,000

// ---------------- tiling ----------------
#define NT   7            // N tiles of 8 fm (56, fm 50..55 zero)
#define NC   15           // K chunks of 16 (K = 240 exact)
#define WIN_BLK 64        // pool windows per block (256 ow)
#define CSTAGE 304        // staged x cols per row (256 + 39 halo + pad)
#define XPITCH 152        // u32 words per row per phase array
#define XROWU32 (9*XPITCH)        // 1368 u32 per phase array
#define BFRAG_SEC (NC*NT*64)      // u32 per section = 6720 (26,880 B)
#define CAPFIX 65536
#define FIXCAP 1024               // per-block smem band list

// smem layout (bytes)
#define SM_XB   0                          // 2 * 1368 u32 = 10,944 B
#define SM_B    10944                      // 26,880 B
#define SM_POOL 37824                      // 50 * 65 f32 = 13,000 B
#define SM_KEY  50824
#define SM_CNT  50828
#define SM_LIST 50832                      // FIXCAP u32 = 4096 B
#define SM_TOTAL 54976

__device__ int g_key[NSEC];
__device__ int g_nfix;
__device__ int g_fixlist[CAPFIX];
__device__ __align__(16) unsigned g_bfrag[NSEC*BFRAG_SEC];

// ---------------- helpers ----------------
__device__ __forceinline__ void mma16816(float* d, const unsigned* a,
                                         const unsigned* b) {
    asm volatile(
        "mma.sync.aligned.m16n8k16.row.col.f32.bf16.bf16.f32 "
        "{%0,%1,%2,%3}, {%4,%5,%6,%7}, {%8,%9}, {%0,%1,%2,%3};"
        : "+f"(d[0]), "+f"(d[1]), "+f"(d[2]), "+f"(d[3])
        : "r"(a[0]), "r"(a[1]), "r"(a[2]), "r"(a[3]), "r"(b[0]), "r"(b[1]));
}

// Exact potential in the reference-matching fp32 chain order
// (kh outer ascending, kw inner ascending, single fmaf chain).
__device__ __forceinline__ float exact_cell(const float* __restrict__ x,
                                            const float* __restrict__ W,
                                            int sec, int t, int fm,
                                            int oh, int ow) {
    const float* xg = x + (t*H_ + 4*sec)*WD_;
    const float* wv = W + (sec*FM_ + fm)*240;
    float acc = 0.0f;
#pragma unroll
    for (int kh = 0; kh < KH_; ++kh) {
        const float* xr = xg + (oh + kh)*WD_ + ow;
        const float* wr = wv + kh*KW_;
#pragma unroll 8
        for (int kw = 0; kw < KW_; ++kw)
            acc = fmaf(__ldg(xr + kw), __ldg(wr + kw), acc);
    }
    return acc;
}

// ---------------- kernels ----------------
__global__ void init_keys_kernel() {
    if (threadIdx.x < NSEC) g_key[threadIdx.x] = INT_MAX;
    if (threadIdx.x == 0) g_nfix = 0;
}

// Pre-convert weights (bf16) into per-lane mma B-fragment layout.
__global__ void prep_bfrag_kernel(const float* __restrict__ W) {
    int sec = blockIdx.x;
    for (int idx = threadIdx.x; idx < NC*NT*32; idx += 256) {
        int c  = idx / (NT*32);
        int r  = idx - c*(NT*32);
        int nt = r >> 5;
        int l  = r & 31;
        int q = l & 3, g = l >> 2;
        int n = nt*8 + g;
        int k0 = 16*c + 2*q;
        unsigned short u[4];
#pragma unroll
        for (int e = 0; e < 4; ++e) {
            int k = k0 + (e >> 1)*8 + (e & 1);
            float wv = (n < FM_) ? W[sec*(FM_*KH_*KW_) + n*240 + k] : 0.0f;
            u[e] = __bfloat16_as_ushort(__float2bfloat16(wv));
        }
        int base = ((sec*NC + c)*NT + nt)*64 + l*2;
        g_bfrag[base]     = (unsigned)u[0] | ((unsigned)u[1] << 16);
        g_bfrag[base + 1] = (unsigned)u[2] | ((unsigned)u[3] << 16);
    }
}

__global__ __launch_bounds__(256, 2)
void conv_mma_kernel(const float* __restrict__ x,
                     const float* __restrict__ W,
                     float* __restrict__ out) {
    extern __shared__ unsigned char sm[];
    unsigned* xs = (unsigned*)(sm + SM_XB);
    unsigned* sb = (unsigned*)(sm + SM_B);
    float*  pool = (float*)(sm + SM_POOL);
    int*    skey = (int*)(sm + SM_KEY);
    int*    scnt = (int*)(sm + SM_CNT);
    unsigned* slist = (unsigned*)(sm + SM_LIST);

    const int tid = threadIdx.x, wid = tid >> 5, lane = tid & 31;
    const int bx  = blockIdx.x;
    const int sec = bx / (T_*8);
    const int rem = bx - sec*(T_*8);
    const int t   = rem >> 3;
    const int chk = rem & 7;
    const int col0 = chk << 8;           // 256 ow per block
    const int wgbase = chk << 6;         // 64 windows per block

    if (tid == 0) { *skey = INT_MAX; *scnt = 0; }

    // ---- stage B fragments (prebuilt, per-lane layout) ----
    {
        const float4* src = (const float4*)(g_bfrag + sec*BFRAG_SEC);
        float4* dst = (float4*)sb;
        for (int i = tid; i < BFRAG_SEC/4; i += 256) dst[i] = src[i];
    }
    // ---- stage x: bf16, 2 phases (aligned u32-pair arrays) ----
    {
        unsigned short* xh = (unsigned short*)xs;
        const float* xg = x + (t*H_ + 4*sec) * WD_;
        for (int i = tid; i < 9*CSTAGE; i += 256) {
            int r = i / CSTAGE;
            int cl = i - r*CSTAGE;
            int gc = col0 + cl;
            float v = (gc < WD_) ? xg[r*WD_ + gc] : 0.0f;
            unsigned short u = __bfloat16_as_ushort(__float2bfloat16(v));
            xh[r*2*XPITCH + cl] = u;                          // phase 0
            if (cl) xh[(9 + r)*2*XPITCH + cl - 1] = u;        // phase 1
        }
    }
    __syncthreads();

    const int q = lane & 3, g = lane >> 2;
    const int oh = g >> 2, ow_in = g & 3;
    const int phase = ow_in & 1;
    const unsigned* xp = xs + phase*XROWU32;
    const unsigned long long* sb64 = (const unsigned long long*)sb;

#pragma unroll 1
    for (int pass = 0; pass < 4; ++pass) {
        const int wl0 = wid*8 + pass*2;
        float d[2][NT][4];
#pragma unroll
        for (int w2 = 0; w2 < 2; ++w2)
#pragma unroll
            for (int nt = 0; nt < NT; ++nt)
#pragma unroll
                for (int j = 0; j < 4; ++j) d[w2][nt][j] = 0.0f;

        int wordb[2];
#pragma unroll
        for (int w2 = 0; w2 < 2; ++w2)
            wordb[w2] = ((wl0 + w2)*4 + ow_in + 2*q) >> 1;

#pragma unroll 1
        for (int c = 0; c < NC; ++c) {
            int kh0 = (2*c) / 5;
            int wo0 = 8*c - 20*kh0;
            int kh8 = (2*c + 1) / 5;
            int wo8 = 8*c + 4 - 20*kh8;

            unsigned long long bb[NT];
#pragma unroll
            for (int nt = 0; nt < NT; ++nt)
                bb[nt] = sb64[(c*NT + nt)*32 + lane];

#pragma unroll
            for (int w2 = 0; w2 < 2; ++w2) {
                int o0 = (oh + kh0)*XPITCH + wordb[w2] + wo0;
                int o8 = (oh + kh8)*XPITCH + wordb[w2] + wo8;
                unsigned a[4];
                a[0] = xp[o0];
                a[1] = xp[o0 + 2*XPITCH];
                a[2] = xp[o8];
                a[3] = xp[o8 + 2*XPITCH];
#pragma unroll
                for (int nt = 0; nt < NT; ++nt)
                    mma16816(d[w2][nt], a, (const unsigned*)&bb[nt]);
            }
        }

        // ---- epilogue: dual-threshold + 4x4 pool + band listing ----
#pragma unroll
        for (int w2 = 0; w2 < 2; ++w2) {
            const int wloc = wl0 + w2;
            const int wg = wgbase + wloc;
            const bool vw = (wg < WP_);
            unsigned long long mdef = 0ull;
#pragma unroll
            for (int nt = 0; nt < NT; ++nt) {
                unsigned bd[4], bm[4];
#pragma unroll
                for (int j = 0; j < 4; ++j) {
                    bd[j] = __ballot_sync(0xffffffffu,
                                          d[w2][nt][j] > THRESHF + DELTA);
                    bm[j] = __ballot_sync(0xffffffffu,
                                          d[w2][nt][j] > THRESHF - DELTA);
                }
#pragma unroll
                for (int par = 0; par < 2; ++par) {
                    unsigned dlo = bd[par], dhi = bd[par + 2];
                    unsigned blo = bm[par], bhi = bm[par + 2];
                    unsigned danys = dlo | dhi, banys = blo | bhi;
#pragma unroll
                    for (int u = 0; u < 4; ++u) {
                        unsigned sel = 0x11111111u << u;
                        bool def = (danys & sel) != 0;
                        if (def) mdef |= 1ull << (nt*8 + 2*u + par);
                        if (vw && !def && (banys & sel) != 0 && lane == 0) {
                            // build per-cell band mask (rows 0..15)
                            unsigned vl = (blo >> u) & 0x11111111u;
                            unsigned vh = (bhi >> u) & 0x11111111u;
                            unsigned cm = 0;
#pragma unroll
                            for (int g2 = 0; g2 < 8; ++g2) {
                                cm |= ((vl >> (4*g2)) & 1u) << g2;
                                cm |= ((vh >> (4*g2)) & 1u) << (g2 + 8);
                            }
                            int fm = nt*8 + 2*u + par;
                            int idx = atomicAdd(scnt, 1);
                            if (idx < FIXCAP)
                                slist[idx] = ((unsigned)wloc << 22)
                                           | ((unsigned)fm << 16) | cm;
                            else {
                                int gi = atomicAdd(&g_nfix, 1);
                                if (gi < CAPFIX)
                                    g_fixlist[gi] =
                                        (((sec*T_ + t)*64 + fm) << 9) | wg;
                            }
                        }
                    }
                }
            }
            if (vw) {
                pool[lane*65 + wloc] = ((mdef >> lane) & 1ull) ? 1.0f : 0.0f;
                if (lane < FM_ - 32)
                    pool[(lane + 32)*65 + wloc] =
                        ((mdef >> (lane + 32)) & 1ull) ? 1.0f : 0.0f;
                if (lane == 0 && mdef)
                    atomicMin(skey,
                        (int)((__ffsll((long long)mdef) - 1)*WP_ + wg));
            }
        }
    }
    __syncthreads();

    // ---- in-block exact fixup of band cells (overlaps other CTAs' MMA) ----
    {
        int nfx = *scnt;
        if (nfx > FIXCAP) nfx = FIXCAP;
        for (int e = wid; e < nfx; e += 8) {
            unsigned rec = slist[e];
            int wloc = rec >> 22;
            int fm = (rec >> 16) & 63;
            unsigned cm = rec & 0xFFFFu;
            bool fire = false;
            if (lane < 16 && ((cm >> lane) & 1u)) {
                int ohc = lane >> 2;
                int ow = (wgbase + wloc)*4 + (lane & 3);
                fire = exact_cell(x, W, sec, t, fm, ohc, ow) > THRESHF;
            }
            if (fire) {
                pool[fm*65 + wloc] = 1.0f;
                atomicMin(skey, fm*WP_ + wgbase + wloc);
            }
        }
    }
    __syncthreads();

    // ---- coalesced pooled store + winner key ----
    for (int i = tid; i < FM_*WIN_BLK; i += 256) {
        int fm = i >> 6, w = i & 63;
        if (wgbase + w < WP_)
            out[((sec*T_ + t)*FM_ + fm)*WP_ + wgbase + w] = pool[fm*65 + w];
    }
    if (tid == 0 && *skey != INT_MAX)
        atomicMin(&g_key[sec], (t << 15) | *skey);
}

// Safety net for smem-list overflow (expected n = 0).
__global__ void fixup_kernel(const float* __restrict__ x,
                             const float* __restrict__ W,
                             float* __restrict__ out) {
    int n = g_nfix;
    if (n > CAPFIX) n = CAPFIX;
    int lane = threadIdx.x & 31;
    int warp = (blockIdx.x*blockDim.x + threadIdx.x) >> 5;
    int nwarp = (gridDim.x*blockDim.x) >> 5;
    for (int e = warp; e < n; e += nwarp) {
        int rec = g_fixlist[e];
        int wg = rec & 511;
        int sf = rec >> 9;
        int fm = sf & 63;
        int st = sf >> 6;
        int sec = st / T_, t = st - sec*T_;
        bool fire = false;
        if (lane < 16) {
            int ohc = lane >> 2;
            int ow = wg*4 + (lane & 3);
            fire = exact_cell(x, W, sec, t, fm, ohc, ow) > THRESHF;
        }
        unsigned bal = __ballot_sync(0xffffffffu, fire);
        if (bal && lane == 0) {
            out[((sec*T_ + t)*FM_ + fm)*WP_ + wg] = 1.0f;
            atomicMin(&g_key[sec], (t << 15) | (fm*WP_ + wg));
        }
    }
}

__global__ void finalize_kernel(float* __restrict__ out, long long out_size) {
    int s = threadIdx.x;
    if (s < NSEC && out_size >= (long long)(POOLED_ELEMS + NSEC)) {
        int k = g_key[s];
        out[POOLED_ELEMS + s] = (k == INT_MAX) ? -1.0f
                                               : (float)((k & 32767) / WP_);
    }
}

extern "C" void kernel_launch(void* const* d_in, const int* in_sizes, int n_in,
                              void* d_out, int out_size) {
    const float* x = (const float*)d_in[0];
    const float* W = (const float*)d_in[1];
    if (n_in >= 2 && in_sizes[0] == NSEC*FM_*KH_*KW_) {
        const float* tmp = x; x = W; W = tmp;
    }
    float* out = (float*)d_out;

    cudaFuncSetAttribute(conv_mma_kernel,
                         cudaFuncAttributeMaxDynamicSharedMemorySize, SM_TOTAL);

    init_keys_kernel<<<1, 32>>>();
    prep_bfrag_kernel<<<NSEC, 256>>>(W);
    conv_mma_kernel<<<NSEC*T_*8, 256, SM_TOTAL>>>(x, W, out);
    fixup_kernel<<<64, 128>>>(x, W, out);
    finalize_kernel<<<1, 32>>>(out, (long long)out_size);
}

// round 16
// speedup vs baseline: 2.7276x; 2.7276x over previous
#include <cuda_runtime.h>
#include <cuda_bf16.h>
#include <climits>
#include <stdint.h>

// ---------------- problem constants ----------------
#define NSEC 9
#define T_   30
#define H_   41
#define WD_  2048
#define FM_  50
#define KH_  6
#define KW_  40
#define WP_  502
#define THRESHF 23.0f
#define DELTA  0.30f
#define POOLED_ELEMS (NSEC*T_*FM_*WP_)   // 6,777,000

// ---------------- tiling ----------------
#define NT   7            // N tiles of 8 fm (56, fm 50..55 zero)
#define NC   15           // K chunks of 16 (K = 240 exact)
#define WIN_BLK 64        // pool windows per block (256 ow)
#define CSTAGE 304        // staged x cols per row (256 + 39 halo + pad)
#define XPITCH 152        // u32 words per row per phase array
#define XROWU32 (9*XPITCH)        // 1368 u32 per phase array
#define BFRAG_SEC (NC*NT*64)      // u32 per section = 6720 (26,880 B)
#define CAPFIX 262144             // entry pairs (uint2)

// smem layout (bytes)
#define SM_XB    0                         // 2 * 1368 u32 = 10,944 B
#define SM_B     10944                     // 26,880 B
#define SM_POOL  37824                     // 50 * 65 f32 = 13,000 B
#define SM_KEY   50824
#define SM_STASH 50832                     // 8 warps * 7 nt * 16B = 896 B
#define SM_TOTAL 51760

__device__ int g_key[NSEC];
__device__ int g_nfix;
__device__ uint2 g_fixlist[CAPFIX];
__device__ __align__(16) unsigned g_bfrag[NSEC*BFRAG_SEC];

// ---------------- helpers ----------------
__device__ __forceinline__ void mma16816(float* d, const unsigned* a,
                                         const unsigned* b) {
    asm volatile(
        "mma.sync.aligned.m16n8k16.row.col.f32.bf16.bf16.f32 "
        "{%0,%1,%2,%3}, {%4,%5,%6,%7}, {%8,%9}, {%0,%1,%2,%3};"
        : "+f"(d[0]), "+f"(d[1]), "+f"(d[2]), "+f"(d[3])
        : "r"(a[0]), "r"(a[1]), "r"(a[2]), "r"(a[3]), "r"(b[0]), "r"(b[1]));
}

// gather bits {0,4,8,...,28} of v into bits 0..7
__device__ __forceinline__ unsigned gather8(unsigned v) {
    v = (v | (v >> 3))  & 0x03030303u;
    v = (v | (v >> 6))  & 0x000F000Fu;
    v = (v | (v >> 12)) & 0xFFu;
    return v;
}

// ---------------- kernels ----------------
__global__ void init_keys_kernel() {
    if (threadIdx.x < NSEC) g_key[threadIdx.x] = INT_MAX;
    if (threadIdx.x == 0) g_nfix = 0;
}

// Pre-convert weights (bf16) into per-lane mma B-fragment layout.
__global__ void prep_bfrag_kernel(const float* __restrict__ W) {
    int sec = blockIdx.x;
    for (int idx = threadIdx.x; idx < NC*NT*32; idx += 256) {
        int c  = idx / (NT*32);
        int r  = idx - c*(NT*32);
        int nt = r >> 5;
        int l  = r & 31;
        int q = l & 3, g = l >> 2;
        int n = nt*8 + g;
        int k0 = 16*c + 2*q;
        unsigned short u[4];
#pragma unroll
        for (int e = 0; e < 4; ++e) {
            int k = k0 + (e >> 1)*8 + (e & 1);
            float wv = (n < FM_) ? W[sec*(FM_*KH_*KW_) + n*240 + k] : 0.0f;
            u[e] = __bfloat16_as_ushort(__float2bfloat16(wv));
        }
        int base = ((sec*NC + c)*NT + nt)*64 + l*2;
        g_bfrag[base]     = (unsigned)u[0] | ((unsigned)u[1] << 16);
        g_bfrag[base + 1] = (unsigned)u[2] | ((unsigned)u[3] << 16);
    }
}

__global__ __launch_bounds__(256, 2)
void conv_mma_kernel(const float* __restrict__ x, float* __restrict__ out) {
    extern __shared__ unsigned char sm[];
    unsigned* xs = (unsigned*)(sm + SM_XB);
    unsigned* sb = (unsigned*)(sm + SM_B);
    float*  pool = (float*)(sm + SM_POOL);
    int*    skey = (int*)(sm + SM_KEY);
    uint4*  stash = (uint4*)(sm + SM_STASH);

    const int tid = threadIdx.x, wid = tid >> 5, lane = tid & 31;
    const int bx  = blockIdx.x;
    const int sec = bx / (T_*8);
    const int rem = bx - sec*(T_*8);
    const int t   = rem >> 3;
    const int chk = rem & 7;
    const int col0 = chk << 8;           // 256 ow per block
    const int wgbase = chk << 6;         // 64 windows per block

    if (tid == 0) *skey = INT_MAX;

    // ---- stage B fragments (prebuilt, per-lane layout) ----
    {
        const float4* src = (const float4*)(g_bfrag + sec*BFRAG_SEC);
        float4* dst = (float4*)sb;
        for (int i = tid; i < BFRAG_SEC/4; i += 256) dst[i] = src[i];
    }
    // ---- stage x: bf16, 2 phases (aligned u32-pair arrays) ----
    {
        unsigned short* xh = (unsigned short*)xs;
        const float* xg = x + (t*H_ + 4*sec) * WD_;
        for (int i = tid; i < 9*CSTAGE; i += 256) {
            int r = i / CSTAGE;
            int cl = i - r*CSTAGE;
            int gc = col0 + cl;
            float v = (gc < WD_) ? xg[r*WD_ + gc] : 0.0f;
            unsigned short u = __bfloat16_as_ushort(__float2bfloat16(v));
            xh[r*2*XPITCH + cl] = u;                          // phase 0
            if (cl) xh[(9 + r)*2*XPITCH + cl - 1] = u;        // phase 1
        }
    }
    __syncthreads();

    const int q = lane & 3, g = lane >> 2;
    const int oh = g >> 2, ow_in = g & 3;
    const int phase = ow_in & 1;
    const unsigned* xp = xs + phase*XROWU32;
    const unsigned long long* sb64 = (const unsigned long long*)sb;

#pragma unroll 1
    for (int pass = 0; pass < 4; ++pass) {
        const int wl0 = wid*8 + pass*2;
        float d[2][NT][4];
#pragma unroll
        for (int w2 = 0; w2 < 2; ++w2)
#pragma unroll
            for (int nt = 0; nt < NT; ++nt)
#pragma unroll
                for (int j = 0; j < 4; ++j) d[w2][nt][j] = 0.0f;

        int wordb[2];
#pragma unroll
        for (int w2 = 0; w2 < 2; ++w2)
            wordb[w2] = ((wl0 + w2)*4 + ow_in + 2*q) >> 1;

#pragma unroll 1
        for (int c = 0; c < NC; ++c) {
            int kh0 = (2*c) / 5;
            int wo0 = 8*c - 20*kh0;
            int kh8 = (2*c + 1) / 5;
            int wo8 = 8*c + 4 - 20*kh8;

            unsigned long long bb[NT];
#pragma unroll
            for (int nt = 0; nt < NT; ++nt)
                bb[nt] = sb64[(c*NT + nt)*32 + lane];

#pragma unroll
            for (int w2 = 0; w2 < 2; ++w2) {
                int o0 = (oh + kh0)*XPITCH + wordb[w2] + wo0;
                int o8 = (oh + kh8)*XPITCH + wordb[w2] + wo8;
                unsigned a[4];
                a[0] = xp[o0];
                a[1] = xp[o0 + 2*XPITCH];
                a[2] = xp[o8];
                a[3] = xp[o8 + 2*XPITCH];
#pragma unroll
                for (int nt = 0; nt < NT; ++nt)
                    mma16816(d[w2][nt], a, (const unsigned*)&bb[nt]);
            }
        }

        // ---- epilogue: dual-threshold + 4x4 pool via ballots ----
#pragma unroll
        for (int w2 = 0; w2 < 2; ++w2) {
            unsigned long long mdef = 0ull, mband = 0ull;
#pragma unroll
            for (int nt = 0; nt < NT; ++nt) {
                unsigned bd[4], bm[4];
#pragma unroll
                for (int j = 0; j < 4; ++j) {
                    bd[j] = __ballot_sync(0xffffffffu,
                                          d[w2][nt][j] > THRESHF + DELTA);
                    bm[j] = __ballot_sync(0xffffffffu,
                                          d[w2][nt][j] > THRESHF - DELTA);
                }
                if (lane == 0)   // stash band ballots for cellmask listing
                    stash[wid*NT + nt] = make_uint4(bm[0], bm[1], bm[2], bm[3]);
                unsigned ed = bd[0] | bd[2], od = bd[1] | bd[3];
                unsigned eb = bm[0] | bm[2], ob = bm[1] | bm[3];
#pragma unroll
                for (int u = 0; u < 4; ++u) {
                    unsigned sel = 0x11111111u << u;
                    if (ed & sel) mdef  |= 1ull << (nt*8 + 2*u);
                    if (od & sel) mdef  |= 1ull << (nt*8 + 2*u + 1);
                    if (eb & sel) mband |= 1ull << (nt*8 + 2*u);
                    if (ob & sel) mband |= 1ull << (nt*8 + 2*u + 1);
                }
            }
            int wloc = wl0 + w2;
            int wg = wgbase + wloc;
            if (wg < WP_) {
                pool[lane*65 + wloc] = ((mdef >> lane) & 1ull) ? 1.0f : 0.0f;
                if (lane < FM_ - 32)
                    pool[(lane + 32)*65 + wloc] =
                        ((mdef >> (lane + 32)) & 1ull) ? 1.0f : 0.0f;
                if (lane == 0) {
                    if (mdef)
                        atomicMin(skey,
                            (int)((__ffsll((long long)mdef) - 1)*WP_ + wg));
                    unsigned long long need = mband & ~mdef;
                    if (need) {    // rare: emit per-cell band records
                        int nfm = __popcll(need);
                        int base = atomicAdd(&g_nfix, nfm);
                        unsigned long long m = need;
                        while (m) {
                            int fm = __ffsll((long long)m) - 1;
                            m &= m - 1;
                            if (base < CAPFIX) {
                                int nt2 = fm >> 3, u2 = (fm & 7) >> 1;
                                int par = fm & 1;
                                uint4 s = stash[wid*NT + nt2];
                                unsigned blo = par ? s.y : s.x;
                                unsigned bhi = par ? s.w : s.z;
                                unsigned cm =
                                    gather8((blo >> u2) & 0x11111111u) |
                                    (gather8((bhi >> u2) & 0x11111111u) << 8);
                                g_fixlist[base] = make_uint2(
                                    (((unsigned)((sec*T_ + t)*64 + fm)) << 9)
                                    | (unsigned)wg, cm);
                            }
                            ++base;
                        }
                    }
                }
            }
        }
    }
    __syncthreads();

    // ---- coalesced pooled store + winner key ----
    for (int i = tid; i < FM_*WIN_BLK; i += 256) {
        int fm = i >> 6, w = i & 63;
        if (wgbase + w < WP_)
            out[((sec*T_ + t)*FM_ + fm)*WP_ + wgbase + w] = pool[fm*65 + w];
    }
    if (tid == 0 && *skey != INT_MAX)
        atomicMin(&g_key[sec], (t << 15) | *skey);
}

// Exact recompute of band CELLS only (reference-matching fp32 chain order:
// kh outer ascending, kw inner ascending, single fmaf chain per cell).
// Two entries per warp (lanes 0-15 / 16-31); avg ~1 active lane per entry.
__global__ void fixup_kernel(const float* __restrict__ x,
                             const float* __restrict__ W,
                             float* __restrict__ out) {
    int n = g_nfix;
    if (n > CAPFIX) n = CAPFIX;
    int lane = threadIdx.x & 31;
    int L = lane & 15;
    int half = lane >> 4;
    int warp = (blockIdx.x*blockDim.x + threadIdx.x) >> 5;
    int nwarp = (gridDim.x*blockDim.x) >> 5;
    for (int e0 = warp*2; e0 < n; e0 += nwarp*2) {
        int e = e0 + half;
        if (e >= n) continue;
        uint2 rc = g_fixlist[e];
        unsigned rec = rc.x, cm = rc.y;
        if (!((cm >> L) & 1u)) continue;
        int wg = rec & 511;
        int sf = rec >> 9;
        int fm = sf & 63;
        int st = sf >> 6;
        int sec = st / T_, t = st - sec*T_;
        int ohc = L >> 2;
        int ow = wg*4 + (L & 3);
        const float* xg = x + (t*H_ + 4*sec)*WD_;
        const float* wv = W + (sec*FM_ + fm)*240;
        float acc = 0.0f;
#pragma unroll
        for (int kh = 0; kh < KH_; ++kh) {
            const float* xr = xg + (ohc + kh)*WD_ + ow;
            const float* wr = wv + kh*KW_;
#pragma unroll 8
            for (int kw = 0; kw < KW_; ++kw)
                acc = fmaf(__ldg(xr + kw), __ldg(wr + kw), acc);
        }
        if (acc > THRESHF) {
            out[((sec*T_ + t)*FM_ + fm)*WP_ + wg] = 1.0f;   // idempotent
            atomicMin(&g_key[sec], (t << 15) | (fm*WP_ + wg));
        }
    }
}

__global__ void finalize_kernel(float* __restrict__ out, long long out_size) {
    int s = threadIdx.x;
    if (s < NSEC && out_size >= (long long)(POOLED_ELEMS + NSEC)) {
        int k = g_key[s];
        out[POOLED_ELEMS + s] = (k == INT_MAX) ? -1.0f
                                               : (float)((k & 32767) / WP_);
    }
}

extern "C" void kernel_launch(void* const* d_in, const int* in_sizes, int n_in,
                              void* d_out, int out_size) {
    const float* x = (const float*)d_in[0];
    const float* W = (const float*)d_in[1];
    if (n_in >= 2 && in_sizes[0] == NSEC*FM_*KH_*KW_) {
        const float* tmp = x; x = W; W = tmp;
    }
    float* out = (float*)d_out;

    cudaFuncSetAttribute(conv_mma_kernel,
                         cudaFuncAttributeMaxDynamicSharedMemorySize, SM_TOTAL);

    init_keys_kernel<<<1, 32>>>();
    prep_bfrag_kernel<<<NSEC, 256>>>(W);
    conv_mma_kernel<<<NSEC*T_*8, 256, SM_TOTAL>>>(x, out);
    fixup_kernel<<<1184, 128>>>(x, W, out);
    finalize_kernel<<<1, 32>>>(out, (long long)out_size);
}